// round 8
// baseline (speedup 1.0000x reference)
#include <cuda_runtime.h>
#include <cuda_bf16.h>
#include <cstdint>
#include <cstring>

// Problem constants
#define T_ROWS   8192
#define KDIM     4096
#define NI       63
#define NPAD     64
#define NLEAF    64
#define NCLS     10

// Tiling
#define KSPLIT   2
#define KHALF    (KDIM / KSPLIT)   // 2048
#define BM       32
#define BK       64
#define NKT_S    (KHALF / BK)      // 32 k-tiles per CTA
#define THREADS  256               // 8 warps: (kh, mw, nh)
#define STAGES   4                 // 4 buffers, 3 groups in flight

#define XROW_WORDS 72              // fp32 words per X smem row (288B, conflict-free LDS.64)
#define XSTG_WORDS (BM * XROW_WORDS)          // 2304 words = 9216 B
#define WSTG_BYTES (NPAD * 128)               // 8192 B (64 rows x 128B, swizzled)
#define DYN_SMEM   (STAGES * (XSTG_WORDS * 4 + WSTG_BYTES))   // 69632 B -> 3 CTAs/SM
#define SZ         68              // Z-combine smem stride (words): 16B-aligned rows

// Scratch (allocation-free rule: __device__ globals)
__device__ __nv_bfloat16 g_Wbf[NPAD * KDIM];
__device__ float         g_leaf_r[NLEAF];
__device__ float         g_Z[KSPLIT][T_ROWS][NPAD];   // 4MB partial logits

// ---------------------------------------------------------------------------
// Prep: W -> bf16 (padded to 64 rows), leaf_r, zero output scalar.
// ---------------------------------------------------------------------------
__global__ void prep_kernel(const float* __restrict__ W,
                            const float* __restrict__ leaf_dist,
                            const float* __restrict__ class_reward,
                            float* __restrict__ out) {
    int idx  = blockIdx.x * blockDim.x + threadIdx.x;
    int base = idx * 4;
    if (base < NPAD * KDIM) {
        int n = base / KDIM;
        int k = base - n * KDIM;
        float4 v = make_float4(0.f, 0.f, 0.f, 0.f);
        if (n < NI) v = *reinterpret_cast<const float4*>(W + n * KDIM + k);
        __nv_bfloat162 lo = __floats2bfloat162_rn(v.x, v.y);
        __nv_bfloat162 hi = __floats2bfloat162_rn(v.z, v.w);
        uint32_t ulo, uhi;
        memcpy(&ulo, &lo, 4);
        memcpy(&uhi, &hi, 4);
        *reinterpret_cast<uint2*>(g_Wbf + base) = make_uint2(ulo, uhi);
    }
    if (blockIdx.x == 0) {
        int t = threadIdx.x;
        if (t < NLEAF) {
            const float* ld = leaf_dist + t * NCLS;
            float mx = ld[0];
            #pragma unroll
            for (int c = 1; c < NCLS; ++c) mx = fmaxf(mx, ld[c]);
            float s = 0.f, r = 0.f;
            #pragma unroll
            for (int c = 0; c < NCLS; ++c) {
                float e = __expf(ld[c] - mx);
                s += e;
                r += e * class_reward[c];
            }
            g_leaf_r[t] = r / s;
        }
        if (t == 0) out[0] = 0.f;
    }
}

// ---------------------------------------------------------------------------
// Helpers
// ---------------------------------------------------------------------------
__device__ __forceinline__ uint32_t smem_u32(const void* p) {
    return (uint32_t)__cvta_generic_to_shared(p);
}
__device__ __forceinline__ void cp16(void* dst, const void* src) {
    uint32_t d = smem_u32(dst);
    asm volatile("cp.async.cg.shared.global [%0], [%1], 16;\n" :: "r"(d), "l"(src));
}
__device__ __forceinline__ uint32_t pack_bf16(float x, float y) {
    __nv_bfloat162 h = __floats2bfloat162_rn(x, y);
    uint32_t u;
    memcpy(&u, &h, 4);
    return u;
}

// ---------------------------------------------------------------------------
// Main GEMM: K-split x2, BM=32, 256 threads, 3 CTAs/SM. cp.async 4-stage
// pipeline; split-k-in-tile (kh); writes partial logits to g_Z[ks].
// ---------------------------------------------------------------------------
__global__ __launch_bounds__(THREADS, 3)
void sdt_main(const float* __restrict__ X) {
    extern __shared__ __align__(16) unsigned char dynsm[];
    float*         Xs  = reinterpret_cast<float*>(dynsm);
    unsigned char* Wsb = dynsm + STAGES * XSTG_WORDS * 4;
    float*         Zs  = reinterpret_cast<float*>(dynsm);   // combine buffer, stride SZ

    const int tid  = threadIdx.x;
    const int lane = tid & 31;
    const int warp = tid >> 5;         // 0..7
    const int kh   = warp >> 2;        // 0..1 : kk half
    const int mw   = (warp >> 1) & 1;  // 0..1 : 16-row slab
    const int nh   = warp & 1;         // 0..1 : 32-col half
    const int ks   = blockIdx.x & 1;   // K-split half
    const int mt   = blockIdx.x >> 1;  // M tile
    const int m0   = mt * BM;

    const float*         Xg = X + (size_t)m0 * KDIM + ks * KHALF;
    const __nv_bfloat16* Wg = g_Wbf + ks * KHALF;

    // ---- stage issue: X: 2 x 16B, W: 2 x 16B per thread ----
    auto issue_stage = [&](int kt) {
        if (kt < NKT_S) {
            unsigned char* xb = reinterpret_cast<unsigned char*>(Xs + (kt % STAGES) * XSTG_WORDS);
            const float*   xs = Xg + kt * BK;
            #pragma unroll
            for (int i = 0; i < 2; ++i) {
                int c   = tid + i * 256;          // 0..511
                int row = c >> 4;                 // 0..31
                int gr  = c & 15;
                cp16(xb + row * (XROW_WORDS * 4) + gr * 16, xs + row * KDIM + gr * 4);
            }
            unsigned char* wb = Wsb + (kt % STAGES) * WSTG_BYTES;
            const __nv_bfloat16* ws = Wg + kt * BK;
            #pragma unroll
            for (int i = 0; i < 2; ++i) {
                int c   = tid + i * 256;          // 0..511
                int row = c >> 3;                 // 0..63
                int gr  = c & 7;
                cp16(wb + row * 128 + ((gr ^ (row & 7)) * 16), ws + row * KDIM + gr * 8);
            }
        }
        asm volatile("cp.async.commit_group;\n" ::: "memory");
    };

    // prologue: 3 stages in flight
    for (int s = 0; s < STAGES - 1; ++s) issue_stage(s);

    float acc[4][4];
    #pragma unroll
    for (int t = 0; t < 4; ++t)
        #pragma unroll
        for (int c = 0; c < 4; ++c) acc[t][c] = 0.f;

    // lane geometry
    const int aq    = lane >> 2;
    const int at2   = (lane & 3) * 2;
    const int arow  = mw * 16 + aq;
    const int brow0 = nh * 32 + ((lane & 16) >> 1) + (lane & 7);
    const int bksel = (lane & 8) >> 3;
    const int bswz  = lane & 7;

    for (int kt = 0; kt < NKT_S; ++kt) {
        asm volatile("cp.async.wait_group %0;\n" :: "n"(STAGES - 2) : "memory"); // stage kt ready
        __syncthreads();                                                         // oldest buffer free
        issue_stage(kt + STAGES - 1);

        const float*         xb = Xs + (kt % STAGES) * XSTG_WORDS;
        const unsigned char* wb = Wsb + (kt % STAGES) * WSTG_BYTES;

        #pragma unroll
        for (int kx = 0; kx < 2; ++kx) {
            const int kk = kh * 2 + kx;
            // A fragment: 4 x LDS.64 (fp32) + cvt to bf16x2
            const float* pr = xb + arow * XROW_WORDS + kk * 16 + at2;
            float2 v00 = *reinterpret_cast<const float2*>(pr);
            float2 v10 = *reinterpret_cast<const float2*>(pr + 8 * XROW_WORDS);
            float2 v01 = *reinterpret_cast<const float2*>(pr + 8);
            float2 v11 = *reinterpret_cast<const float2*>(pr + 8 * XROW_WORDS + 8);
            uint32_t a0 = pack_bf16(v00.x, v00.y);
            uint32_t a1 = pack_bf16(v10.x, v10.y);
            uint32_t a2 = pack_bf16(v01.x, v01.y);
            uint32_t a3 = pack_bf16(v11.x, v11.y);

            // B fragments: 2 x ldmatrix.x4 from swizzled bf16 W
            uint32_t bb[2][4];
            #pragma unroll
            for (int g = 0; g < 2; ++g) {
                int      row   = brow0 + g * 16;
                uint32_t baddr = smem_u32(wb + row * 128 + (((kk * 2 + bksel) ^ bswz) * 16));
                asm volatile("ldmatrix.sync.aligned.m8n8.x4.shared.b16 {%0,%1,%2,%3}, [%4];\n"
                             : "=r"(bb[g][0]), "=r"(bb[g][1]), "=r"(bb[g][2]), "=r"(bb[g][3])
                             : "r"(baddr));
            }
            #pragma unroll
            for (int t = 0; t < 4; ++t) {
                const int g = t >> 1, p = (t & 1) * 2;
                asm volatile(
                    "mma.sync.aligned.m16n8k16.row.col.f32.bf16.bf16.f32 "
                    "{%0,%1,%2,%3}, {%4,%5,%6,%7}, {%8,%9}, {%0,%1,%2,%3};\n"
                    : "+f"(acc[t][0]), "+f"(acc[t][1]), "+f"(acc[t][2]), "+f"(acc[t][3])
                    : "r"(a0), "r"(a1), "r"(a2), "r"(a3), "r"(bb[g][p]), "r"(bb[g][p + 1]));
            }
        }
    }

    // drain, then all warps done with GEMM smem
    asm volatile("cp.async.wait_group 0;\n" ::: "memory");
    __syncthreads();

    // --- combine kh halves in smem, then store partial logits to g_Z[ks] ---
    if (kh == 0) {
        #pragma unroll
        for (int t = 0; t < 4; ++t) {
            const int ncol = nh * 32 + t * 8 + (lane & 3) * 2;
            const int row  = mw * 16 + (lane >> 2);
            #pragma unroll
            for (int h = 0; h < 2; ++h) {
                const int r = row + h * 8;
                #pragma unroll
                for (int j = 0; j < 2; ++j)
                    Zs[r * SZ + ncol + j] = acc[t][h * 2 + j];
            }
        }
    }
    __syncthreads();
    if (kh == 1) {
        #pragma unroll
        for (int t = 0; t < 4; ++t) {
            const int ncol = nh * 32 + t * 8 + (lane & 3) * 2;
            const int row  = mw * 16 + (lane >> 2);
            #pragma unroll
            for (int h = 0; h < 2; ++h) {
                const int r = row + h * 8;
                #pragma unroll
                for (int j = 0; j < 2; ++j)
                    Zs[r * SZ + ncol + j] += acc[t][h * 2 + j];
            }
        }
    }
    __syncthreads();

    // coalesced float4 copy Zs -> g_Z[ks][m0..m0+31][0..63]
    float* zg = &g_Z[ks][m0][0];
    #pragma unroll
    for (int i = 0; i < 2; ++i) {
        int idx = (tid + i * 256) * 4;        // 0..2047
        int row = idx >> 6;
        int col = idx & 63;
        *reinterpret_cast<float4*>(zg + row * NPAD + col) =
            *reinterpret_cast<const float4*>(Zs + row * SZ + col);
    }
}

// ---------------------------------------------------------------------------
// Epilogue: z = Z0+Z1; P = sigmoid(beta*(z+b)); tree walk; reduce.
// 128 CTAs x 256 threads; CTA handles 64 rows.
// ---------------------------------------------------------------------------
__global__ __launch_bounds__(256)
void sdt_epi(const float* __restrict__ b,
             const float* __restrict__ beta,
             float* __restrict__ out) {
    __shared__ float Ps[64 * (NPAD + 1)];
    __shared__ float s_b[NPAD], s_beta[NPAD];

    const int tid  = threadIdx.x;
    const int lane = tid & 31;
    const int warp = tid >> 5;
    const int r0   = blockIdx.x * 64;

    if (tid < NPAD) {
        s_b[tid]    = (tid < NI) ? b[tid]    : 0.f;
        s_beta[tid] = (tid < NI) ? beta[tid] : 0.f;
    }
    __syncthreads();

    #pragma unroll
    for (int i = 0; i < 4; ++i) {
        int idx = (tid + i * 256) * 4;        // 0..4095
        int row = idx >> 6;
        int col = idx & 63;
        float4 z0 = *reinterpret_cast<const float4*>(&g_Z[0][r0 + row][col]);
        float4 z1 = *reinterpret_cast<const float4*>(&g_Z[1][r0 + row][col]);
        float z[4] = {z0.x + z1.x, z0.y + z1.y, z0.z + z1.z, z0.w + z1.w};
        #pragma unroll
        for (int j = 0; j < 4; ++j) {
            int n = col + j;
            if (n < NI) {
                float u = s_beta[n] * (z[j] + s_b[n]);
                Ps[row * (NPAD + 1) + n] = 1.f / (1.f + __expf(-u));
            }
        }
    }
    __syncthreads();

    // tree walk: 8 warps x 8 rows; lane handles leaves (lane, lane+32)
    const float lr0 = g_leaf_r[lane];
    const float lr1 = g_leaf_r[lane + 32];
    float wsum = 0.f;
    #pragma unroll
    for (int r = 0; r < 8; ++r) {
        const int row = warp * 8 + r;
        const float* Pr = Ps + row * (NPAD + 1);
        float v0 = 1.f, v1 = 1.f;
        const int L0 = lane, L1 = lane + 32;
        #pragma unroll
        for (int k = 0; k < 6; ++k) {
            const int off = (1 << k) - 1;
            const float P0 = Pr[off + (L0 >> (6 - k))];
            const float P1 = Pr[off + (L1 >> (6 - k))];
            v0 *= ((L0 >> (5 - k)) & 1) ? (1.f - P0) : P0;
            v1 *= ((L1 >> (5 - k)) & 1) ? (1.f - P1) : P1;
        }
        wsum += v0 * lr0 + v1 * lr1;
    }
    #pragma unroll
    for (int s = 16; s > 0; s >>= 1)
        wsum += __shfl_down_sync(0xffffffffu, wsum, s);
    if (lane == 0) atomicAdd(out, wsum);
}

// ---------------------------------------------------------------------------
// kernel_launch
// ---------------------------------------------------------------------------
extern "C" void kernel_launch(void* const* d_in, const int* in_sizes, int n_in,
                              void* d_out, int out_size) {
    const float* X    = (const float*)d_in[0];
    const float* W    = (const float*)d_in[1];
    const float* b    = (const float*)d_in[2];
    const float* beta = (const float*)d_in[3];
    const float* leaf = (const float*)d_in[4];
    const float* cls  = (const float*)d_in[5];
    float* out = (float*)d_out;

    cudaFuncSetAttribute(sdt_main, cudaFuncAttributeMaxDynamicSharedMemorySize, DYN_SMEM);

    prep_kernel<<<256, 256>>>(W, leaf, cls, out);
    sdt_main<<<(T_ROWS / BM) * KSPLIT, THREADS, DYN_SMEM>>>(X);
    sdt_epi<<<T_ROWS / 64, 256>>>(b, beta, out);
}

// round 9
// speedup vs baseline: 1.2889x; 1.2889x over previous
#include <cuda_runtime.h>
#include <cuda_bf16.h>
#include <cstdint>
#include <cstring>

// Problem constants
#define T_ROWS   8192
#define KDIM     4096
#define NI       63
#define NPAD     64
#define NLEAF    64
#define NCLS     10

// Tiling: BM=32, BK=128; 8 warps, warp w owns k-slice w*16..w*16+15 of each
// tile and the FULL 32x64 output (no smem read duplication).
#define BM       32
#define BK       128
#define NKT      (KDIM / BK)       // 32 k-tiles
#define THREADS  256
#define STAGES   3                 // 3 buffers, 2 groups in flight

#define XSTRIDE   136              // fp32 words per X smem row (544B, conflict-free LDS.64)
#define XSTG_WORDS (BM * XSTRIDE)  // 4352 words = 17408 B
#define WSTG_BYTES (NPAD * 256)    // 16384 B (64 rows x 256B, swizzled 16B granules)
#define STG_BYTES  (XSTG_WORDS * 4 + WSTG_BYTES)   // 33792
#define DYN_SMEM   (STAGES * STG_BYTES)            // 101376 B -> 2 CTAs/SM

#define CB_STRIDE  72              // combine buffer row stride (words)

// Scratch (allocation-free rule: __device__ globals)
__device__ __nv_bfloat16 g_Wbf[NPAD * KDIM];
__device__ float         g_leaf_r[NLEAF];

// ---------------------------------------------------------------------------
// Prep: W -> bf16 (padded to 64 rows), leaf_r, zero output scalar.
// 64 CTAs x 256 thr, 4 independent float4s per thread (MLP=4).
// ---------------------------------------------------------------------------
__global__ void prep_kernel(const float* __restrict__ W,
                            const float* __restrict__ leaf_dist,
                            const float* __restrict__ class_reward,
                            float* __restrict__ out) {
    int t0 = blockIdx.x * 256 + threadIdx.x;
    float4 v[4];
    int    bases[4];
    #pragma unroll
    for (int i = 0; i < 4; ++i) {
        int idx4 = t0 + i * 16384;          // 0..65535
        int base = idx4 * 4;                // element base
        bases[i] = base;
        int n = base >> 12;                 // /KDIM
        v[i] = (n < NI) ? *reinterpret_cast<const float4*>(W + base)
                        : make_float4(0.f, 0.f, 0.f, 0.f);
    }
    #pragma unroll
    for (int i = 0; i < 4; ++i) {
        __nv_bfloat162 lo = __floats2bfloat162_rn(v[i].x, v[i].y);
        __nv_bfloat162 hi = __floats2bfloat162_rn(v[i].z, v[i].w);
        uint32_t ulo, uhi;
        memcpy(&ulo, &lo, 4);
        memcpy(&uhi, &hi, 4);
        *reinterpret_cast<uint2*>(g_Wbf + bases[i]) = make_uint2(ulo, uhi);
    }
    if (blockIdx.x == 0) {
        int t = threadIdx.x;
        if (t < NLEAF) {
            const float* ld = leaf_dist + t * NCLS;
            float mx = ld[0];
            #pragma unroll
            for (int c = 1; c < NCLS; ++c) mx = fmaxf(mx, ld[c]);
            float s = 0.f, r = 0.f;
            #pragma unroll
            for (int c = 0; c < NCLS; ++c) {
                float e = __expf(ld[c] - mx);
                s += e;
                r += e * class_reward[c];
            }
            g_leaf_r[t] = r / s;
        }
        if (t == 0) out[0] = 0.f;
    }
}

// ---------------------------------------------------------------------------
// Helpers
// ---------------------------------------------------------------------------
__device__ __forceinline__ uint32_t smem_u32(const void* p) {
    return (uint32_t)__cvta_generic_to_shared(p);
}
__device__ __forceinline__ void cp16(void* dst, const void* src) {
    uint32_t d = smem_u32(dst);
    asm volatile("cp.async.cg.shared.global [%0], [%1], 16;\n" :: "r"(d), "l"(src));
}
__device__ __forceinline__ uint32_t pack_bf16(float x, float y) {
    __nv_bfloat162 h = __floats2bfloat162_rn(x, y);
    uint32_t u;
    memcpy(&u, &h, 4);
    return u;
}

// ---------------------------------------------------------------------------
// Main: BM=32/BK=128, 8 warps each owning one k16 slice of the full 32x64
// tile; zero smem read duplication; k-partials combined in smem; fused
// sigmoid + tree epilogue.
// ---------------------------------------------------------------------------
__global__ __launch_bounds__(THREADS, 2)
void sdt_main(const float* __restrict__ X,
              const float* __restrict__ b,
              const float* __restrict__ beta,
              float* __restrict__ out) {
    extern __shared__ __align__(16) unsigned char dynsm[];
    float*         Xs  = reinterpret_cast<float*>(dynsm);
    unsigned char* Wsb = dynsm + STAGES * XSTG_WORDS * 4;
    float*         Cb  = reinterpret_cast<float*>(dynsm);   // combine: [8][32][CB_STRIDE]
    float*         Ps  = reinterpret_cast<float*>(dynsm);   // final P, stride 65 (after combine)

    __shared__ float s_b[NPAD], s_beta[NPAD];

    const int tid  = threadIdx.x;
    const int lane = tid & 31;
    const int warp = tid >> 5;        // 0..7 == k-slice (k16) index within tile
    const int m0   = blockIdx.x * BM;

    if (tid < NPAD) {
        s_b[tid]    = (tid < NI) ? b[tid]    : 0.f;
        s_beta[tid] = (tid < NI) ? beta[tid] : 0.f;
    }

    const float* Xg = X + (size_t)m0 * KDIM;

    // ---- stage issue: X 4 x 16B + W 4 x 16B per thread ----
    auto issue_stage = [&](int kt) {
        if (kt < NKT) {
            unsigned char* xb = dynsm + (kt % STAGES) * XSTG_WORDS * 4;
            const float*   xs = Xg + kt * BK;
            #pragma unroll
            for (int i = 0; i < 4; ++i) {
                int c   = tid + i * 256;     // 0..1023
                int row = c >> 5;            // 0..31
                int gr  = c & 31;            // 16B granule in row
                cp16(xb + row * (XSTRIDE * 4) + gr * 16, xs + row * KDIM + gr * 4);
            }
            unsigned char* wb = Wsb + (kt % STAGES) * WSTG_BYTES;
            const __nv_bfloat16* ws = g_Wbf + kt * BK;
            #pragma unroll
            for (int i = 0; i < 4; ++i) {
                int c   = tid + i * 256;     // 0..1023
                int row = c >> 4;            // 0..63
                int gr  = c & 15;            // 16B granule (16 per 256B row)
                int pos = (gr & 8) | ((gr ^ row) & 7);
                cp16(wb + row * 256 + pos * 16, ws + row * KDIM + gr * 8);
            }
        }
        asm volatile("cp.async.commit_group;\n" ::: "memory");
    };

    // prologue: 2 stages in flight
    issue_stage(0);
    issue_stage(1);

    float acc[2][8][4];   // [m-slab][n8-tile][frag]
    #pragma unroll
    for (int s = 0; s < 2; ++s)
        #pragma unroll
        for (int n = 0; n < 8; ++n)
            #pragma unroll
            for (int c = 0; c < 4; ++c) acc[s][n][c] = 0.f;

    // lane geometry
    const int aq    = lane >> 2;            // A row-in-8
    const int at2   = (lane & 3) * 2;       // A k pair
    const int akoff = warp * 16 + at2;      // word offset of this warp's k-slice
    const int brow  = ((lane & 16) >> 1) + (lane & 7);   // + nt2*16
    const int bgr   = warp * 2 + ((lane & 8) >> 3);      // W granule (0..15)

    for (int kt = 0; kt < NKT; ++kt) {
        asm volatile("cp.async.wait_group 1;\n" ::: "memory");  // stage kt ready
        __syncthreads();                                        // oldest buffer free
        issue_stage(kt + 2);

        const float*         xb = Xs + (kt % STAGES) * XSTG_WORDS;
        const unsigned char* wb = Wsb + (kt % STAGES) * WSTG_BYTES;

        // A fragments for both 16-row slabs of this warp's k-slice
        uint32_t a[2][4];
        #pragma unroll
        for (int s = 0; s < 2; ++s) {
            const float* pr = xb + (s * 16 + aq) * XSTRIDE + akoff;
            float2 v00 = *reinterpret_cast<const float2*>(pr);
            float2 v10 = *reinterpret_cast<const float2*>(pr + 8 * XSTRIDE);
            float2 v01 = *reinterpret_cast<const float2*>(pr + 8);
            float2 v11 = *reinterpret_cast<const float2*>(pr + 8 * XSTRIDE + 8);
            a[s][0] = pack_bf16(v00.x, v00.y);
            a[s][1] = pack_bf16(v10.x, v10.y);
            a[s][2] = pack_bf16(v01.x, v01.y);
            a[s][3] = pack_bf16(v11.x, v11.y);
        }

        // B fragments: 4 x ldmatrix.x4 covering full N=64 for this k-slice
        uint32_t bb[4][4];
        #pragma unroll
        for (int nt2 = 0; nt2 < 4; ++nt2) {
            int      row   = nt2 * 16 + brow;
            int      pos   = (bgr & 8) | ((bgr ^ (row & 7)) & 7);
            uint32_t baddr = smem_u32(wb + row * 256 + pos * 16);
            asm volatile("ldmatrix.sync.aligned.m8n8.x4.shared.b16 {%0,%1,%2,%3}, [%4];\n"
                         : "=r"(bb[nt2][0]), "=r"(bb[nt2][1]), "=r"(bb[nt2][2]), "=r"(bb[nt2][3])
                         : "r"(baddr));
        }

        // 16 MMAs: 2 slabs x 8 n-tiles
        #pragma unroll
        for (int nt2 = 0; nt2 < 4; ++nt2) {
            #pragma unroll
            for (int pn = 0; pn < 2; ++pn) {
                const int n = nt2 * 2 + pn;
                #pragma unroll
                for (int s = 0; s < 2; ++s) {
                    asm volatile(
                        "mma.sync.aligned.m16n8k16.row.col.f32.bf16.bf16.f32 "
                        "{%0,%1,%2,%3}, {%4,%5,%6,%7}, {%8,%9}, {%0,%1,%2,%3};\n"
                        : "+f"(acc[s][n][0]), "+f"(acc[s][n][1]),
                          "+f"(acc[s][n][2]), "+f"(acc[s][n][3])
                        : "r"(a[s][0]), "r"(a[s][1]), "r"(a[s][2]), "r"(a[s][3]),
                          "r"(bb[nt2][pn * 2]), "r"(bb[nt2][pn * 2 + 1]));
                }
            }
        }
    }

    asm volatile("cp.async.wait_group 0;\n" ::: "memory");
    __syncthreads();

    // --- combine: each warp stores its k-partial 32x64 tile ---
    {
        float* wbuf = Cb + warp * (32 * CB_STRIDE);
        #pragma unroll
        for (int s = 0; s < 2; ++s) {
            #pragma unroll
            for (int n = 0; n < 8; ++n) {
                const int col = n * 8 + (lane & 3) * 2;
                const int r0  = s * 16 + (lane >> 2);
                *reinterpret_cast<float2*>(wbuf + r0 * CB_STRIDE + col) =
                    make_float2(acc[s][n][0], acc[s][n][1]);
                *reinterpret_cast<float2*>(wbuf + (r0 + 8) * CB_STRIDE + col) =
                    make_float2(acc[s][n][2], acc[s][n][3]);
            }
        }
    }
    __syncthreads();

    // --- reduce 8 partials, sigmoid, write P (aliases Cb after sync) ---
    float2 zred[4];
    int    prow[4], pcol[4];
    #pragma unroll
    for (int i = 0; i < 4; ++i) {
        int pi  = tid + i * 256;        // 0..1023 pair index
        int row = pi >> 5;              // 0..31
        int col = (pi & 31) * 2;        // 0..62
        float2 zv = make_float2(0.f, 0.f);
        #pragma unroll
        for (int w = 0; w < 8; ++w) {
            float2 p = *reinterpret_cast<const float2*>(
                Cb + w * (32 * CB_STRIDE) + row * CB_STRIDE + col);
            zv.x += p.x;
            zv.y += p.y;
        }
        zred[i] = zv;
        prow[i] = row;
        pcol[i] = col;
    }
    __syncthreads();
    #pragma unroll
    for (int i = 0; i < 4; ++i) {
        #pragma unroll
        for (int j = 0; j < 2; ++j) {
            int n = pcol[i] + j;
            if (n < NI) {
                float z = (j ? zred[i].y : zred[i].x);
                float u = s_beta[n] * (z + s_b[n]);
                Ps[prow[i] * (NPAD + 1) + n] = 1.f / (1.f + __expf(-u));
            }
        }
    }
    __syncthreads();

    // --- tree walk: 8 warps x 4 rows; lane handles leaves (lane, lane+32) ---
    const float lr0 = g_leaf_r[lane];
    const float lr1 = g_leaf_r[lane + 32];
    float wsum = 0.f;
    #pragma unroll
    for (int r = 0; r < 4; ++r) {
        const int row = warp * 4 + r;
        const float* Pr = Ps + row * (NPAD + 1);
        float v0 = 1.f, v1 = 1.f;
        const int L0 = lane, L1 = lane + 32;
        #pragma unroll
        for (int k = 0; k < 6; ++k) {
            const int off = (1 << k) - 1;
            const float P0 = Pr[off + (L0 >> (6 - k))];
            const float P1 = Pr[off + (L1 >> (6 - k))];
            v0 *= ((L0 >> (5 - k)) & 1) ? (1.f - P0) : P0;
            v1 *= ((L1 >> (5 - k)) & 1) ? (1.f - P1) : P1;
        }
        wsum += v0 * lr0 + v1 * lr1;
    }
    #pragma unroll
    for (int s = 16; s > 0; s >>= 1)
        wsum += __shfl_down_sync(0xffffffffu, wsum, s);
    if (lane == 0) atomicAdd(out, wsum);
}

// ---------------------------------------------------------------------------
// kernel_launch
// ---------------------------------------------------------------------------
extern "C" void kernel_launch(void* const* d_in, const int* in_sizes, int n_in,
                              void* d_out, int out_size) {
    const float* X    = (const float*)d_in[0];
    const float* W    = (const float*)d_in[1];
    const float* b    = (const float*)d_in[2];
    const float* beta = (const float*)d_in[3];
    const float* leaf = (const float*)d_in[4];
    const float* cls  = (const float*)d_in[5];
    float* out = (float*)d_out;

    cudaFuncSetAttribute(sdt_main, cudaFuncAttributeMaxDynamicSharedMemorySize, DYN_SMEM);

    prep_kernel<<<64, 256>>>(W, leaf, cls, out);
    sdt_main<<<T_ROWS / BM, THREADS, DYN_SMEM>>>(X, b, beta, out);
}